// round 2
// baseline (speedup 1.0000x reference)
#include <cuda_runtime.h>
#include <cuda_bf16.h>

// Problem shapes (fixed by setup_inputs): T=128, C0=512, C1=1024.
#define C0V 512
#define TV  128
#define C1V 1024

#define WARPS_PER_T   32                       // 32 warps cover the 512 i-values of one t
#define ROWS_PER_WARP (C0V / WARPS_PER_T)      // 16
#define WARPS_PER_BLK 8
#define BLOCKS_PER_T  (WARPS_PER_T / WARPS_PER_BLK)  // 4
#define THREADS 256

// Scratch (allocation-free rule: __device__ globals only)
__device__ double g_S, g_sumR2, g_sumQ2, g_sumSbar2;
__device__ float  g_Qpart[BLOCKS_PER_T][TV][C1V];   // 2 MB partial column-sums

__global__ void lcl_init_kernel() {
    g_S = 0.0; g_sumR2 = 0.0; g_sumQ2 = 0.0; g_sumSbar2 = 0.0;
}

// Pass 1: stream the 256 MB tensor exactly once.
// grid = TV * BLOCKS_PER_T = 512 blocks. Block (t, sub); warp wt = sub*8+warp
// owns rows i in [wt*16, wt*16+16), all at fixed t. Each lane reads the same
// 32 columns of every row -> Q accumulates in registers, zero smem traffic in
// the hot loop, 8 independent float4 loads in flight per lane (MLP=8).
__global__ __launch_bounds__(THREADS) void lcl_pass1(const float* __restrict__ in) {
    __shared__ float qs[C1V];
    const int tid  = threadIdx.x;
    const int t    = blockIdx.x >> 2;
    const int sub  = blockIdx.x & 3;
    const int warp = tid >> 5;
    const int lane = tid & 31;

    for (int j = tid; j < C1V; j += THREADS) qs[j] = 0.f;
    __syncthreads();

    const int wt = sub * WARPS_PER_BLK + warp;

    float q[8][4];
#pragma unroll
    for (int c = 0; c < 8; c++)
#pragma unroll
        for (int k = 0; k < 4; k++) q[c][k] = 0.f;

    float s2 = 0.f;   // per-lane sum of squares
    float r2 = 0.f;   // sum over this warp's rows of (full row sum)^2

    for (int r = 0; r < ROWS_PER_WARP; r++) {
        const int i = wt * ROWS_PER_WARP + r;
        const float4* __restrict__ row =
            (const float4*)(in + (size_t)(i * TV + t) * C1V);
        float rp = 0.f;
#pragma unroll
        for (int c = 0; c < 8; c++) {
            float4 v = row[c * 32 + lane];
            s2 += v.x * v.x + v.y * v.y + v.z * v.z + v.w * v.w;
            rp += v.x + v.y + v.z + v.w;
            q[c][0] += v.x; q[c][1] += v.y; q[c][2] += v.z; q[c][3] += v.w;
        }
#pragma unroll
        for (int o = 16; o > 0; o >>= 1)
            rp += __shfl_xor_sync(0xffffffffu, rp, o);
        r2 += rp * rp;          // identical on all lanes; lane 0 publishes
    }

    // Flush per-lane Q partials into the block accumulator (8 warps collide
    // per address -> smem atomics, 32 per lane, outside the hot loop).
#pragma unroll
    for (int c = 0; c < 8; c++)
#pragma unroll
        for (int k = 0; k < 4; k++)
            atomicAdd(&qs[c * 128 + lane * 4 + k], q[c][k]);

#pragma unroll
    for (int o = 16; o > 0; o >>= 1)
        s2 += __shfl_xor_sync(0xffffffffu, s2, o);
    if (lane == 0) {
        atomicAdd(&g_S, (double)s2);
        atomicAdd(&g_sumR2, (double)r2);
    }

    __syncthreads();
    // Block exclusively owns slice (sub, t): plain vector stores.
    float4* __restrict__ qp = (float4*)g_Qpart[sub][t];
    const float4* __restrict__ qsv = (const float4*)qs;
    for (int j = tid; j < C1V / 4; j += THREADS) qp[j] = qsv[j];
}

// Pass 2: one block per t. Combine the 4 Q slices -> sumQ2, Sbar[t], sumSbar2.
__global__ __launch_bounds__(256) void lcl_pass2() {
    __shared__ float redA[256];
    __shared__ float redB[256];
    const int t = blockIdx.x, tid = threadIdx.x;
    float sq2 = 0.f, sb = 0.f;
    for (int j = tid; j < C1V; j += 256) {
        float v = g_Qpart[0][t][j] + g_Qpart[1][t][j]
                + g_Qpart[2][t][j] + g_Qpart[3][t][j];
        sq2 += v * v;
        sb  += v;
    }
    redA[tid] = sq2; redB[tid] = sb;
    __syncthreads();
    for (int s = 128; s > 0; s >>= 1) {
        if (tid < s) { redA[tid] += redA[tid + s]; redB[tid] += redB[tid + s]; }
        __syncthreads();
    }
    if (tid == 0) {
        atomicAdd(&g_sumQ2, (double)redA[0]);
        double sbar = (double)redB[0];
        atomicAdd(&g_sumSbar2, sbar * sbar);
    }
}

// Pass 3: fold the 4 sufficient statistics into the scalar loss.
__global__ void lcl_finalize(float* __restrict__ out) {
    const double S   = g_S;
    const double R2  = g_sumR2;
    const double Q2  = g_sumQ2;
    const double SB2 = g_sumSbar2;
    const double c0 = (double)C0V, c1 = (double)C1V;

    const double intra  = S - R2 / c1;
    const double inter  = R2 / c1 - SB2 / (c0 * c1);
    const double dintra = S - Q2 / c0;
    const double dinter = Q2 / c0 - SB2 / (c0 * c1);
    const double loss = 0.5 * (intra / inter + dintra / dinter) / (c0 * c1);
    out[0] = (float)loss;
}

extern "C" void kernel_launch(void* const* d_in, const int* in_sizes, int n_in,
                              void* d_out, int out_size) {
    const float* in = (const float*)d_in[0];
    float* out = (float*)d_out;
    (void)in_sizes; (void)n_in; (void)out_size;

    lcl_init_kernel<<<1, 1>>>();
    lcl_pass1<<<TV * BLOCKS_PER_T, THREADS>>>(in);
    lcl_pass2<<<TV, 256>>>();
    lcl_finalize<<<1, 1>>>(out);
}

// round 4
// speedup vs baseline: 1.1434x; 1.1434x over previous
#include <cuda_runtime.h>
#include <cuda_bf16.h>

// Problem shapes (fixed by setup_inputs): T=128, C0=512, C1=1024.
#define C0V 512
#define TV  128
#define C1V 1024

#define BLOCKS_PER_T  8
#define WARPS_PER_BLK 8
#define THREADS 256
#define GRID1 (TV * BLOCKS_PER_T)                     // 1024
#define WARPS_PER_T (BLOCKS_PER_T * WARPS_PER_BLK)    // 64
#define ROWS_PER_WARP (C0V / WARPS_PER_T)             // 8

// Scratch (allocation-free rule: __device__ globals only). No init kernel:
// everything is written with plain stores before it is read.
__device__ float g_Qpart[BLOCKS_PER_T][TV][C1V];   // 4 MB partial column-sums
__device__ float g_Spart[GRID1];                   // per-block sum of squares
__device__ float g_R2part[GRID1];                  // per-block sum of (row sum)^2
__device__ float g_Q2part[TV];                     // per-t sum of Q^2
__device__ float g_SBpart[TV];                     // per-t Sbar
__device__ int   g_ticket = 0;                     // reset by last block each run

// ---------------------------------------------------------------------------
// Pass 1: stream the 256 MB tensor exactly once.
// grid = 1024 blocks. Block b -> (t = b>>3, sub = b&7). Warp wt = sub*8+warp
// owns rows i in [wt*8, wt*8+8) at fixed t. Lane always reads the same 32
// columns -> Q accumulates in registers. Two rows are processed per loop
// iteration: 16 float4 loads issued back-to-back, two independent shuffle
// butterflies interleaved (2x SHFL ILP).
// ---------------------------------------------------------------------------
__global__ __launch_bounds__(THREADS) void lcl_pass1(const float* __restrict__ in) {
    __shared__ float qs[C1V];
    __shared__ float sred[WARPS_PER_BLK];
    __shared__ float rred[WARPS_PER_BLK];

    const int tid  = threadIdx.x;
    const int t    = blockIdx.x >> 3;
    const int sub  = blockIdx.x & 7;
    const int warp = tid >> 5;
    const int lane = tid & 31;

    for (int j = tid; j < C1V; j += THREADS) qs[j] = 0.f;
    __syncthreads();

    const int wt = sub * WARPS_PER_BLK + warp;

    float q[8][4];
#pragma unroll
    for (int c = 0; c < 8; c++)
#pragma unroll
        for (int k = 0; k < 4; k++) q[c][k] = 0.f;

    float s2 = 0.f;   // per-lane sum of squares
    float r2 = 0.f;   // sum over this warp's rows of (full row sum)^2

    for (int r = 0; r < ROWS_PER_WARP; r += 2) {
        const int i0 = wt * ROWS_PER_WARP + r;
        const float4* __restrict__ row0 =
            (const float4*)(in + (size_t)(i0 * TV + t) * C1V);
        const float4* __restrict__ row1 =
            (const float4*)(in + (size_t)((i0 + 1) * TV + t) * C1V);

        float4 a[8], b[8];
#pragma unroll
        for (int c = 0; c < 8; c++) a[c] = row0[c * 32 + lane];
#pragma unroll
        for (int c = 0; c < 8; c++) b[c] = row1[c * 32 + lane];

        float rp0 = 0.f, rp1 = 0.f;
#pragma unroll
        for (int c = 0; c < 8; c++) {
            float4 v = a[c];
            s2  += v.x * v.x + v.y * v.y + v.z * v.z + v.w * v.w;
            rp0 += v.x + v.y + v.z + v.w;
            q[c][0] += v.x; q[c][1] += v.y; q[c][2] += v.z; q[c][3] += v.w;
            float4 w = b[c];
            s2  += w.x * w.x + w.y * w.y + w.z * w.z + w.w * w.w;
            rp1 += w.x + w.y + w.z + w.w;
            q[c][0] += w.x; q[c][1] += w.y; q[c][2] += w.z; q[c][3] += w.w;
        }
        // two independent butterfly chains, interleaved
#pragma unroll
        for (int o = 16; o > 0; o >>= 1) {
            rp0 += __shfl_xor_sync(0xffffffffu, rp0, o);
            rp1 += __shfl_xor_sync(0xffffffffu, rp1, o);
        }
        r2 += rp0 * rp0 + rp1 * rp1;   // identical on all lanes
    }

    // Flush per-lane Q partials into block accumulator (outside hot loop).
#pragma unroll
    for (int c = 0; c < 8; c++)
#pragma unroll
        for (int k = 0; k < 4; k++)
            atomicAdd(&qs[c * 128 + lane * 4 + k], q[c][k]);

#pragma unroll
    for (int o = 16; o > 0; o >>= 1)
        s2 += __shfl_xor_sync(0xffffffffu, s2, o);
    if (lane == 0) { sred[warp] = s2; rred[warp] = r2; }
    __syncthreads();

    if (tid == 0) {
        float ss = 0.f, rr = 0.f;
#pragma unroll
        for (int w = 0; w < WARPS_PER_BLK; w++) { ss += sred[w]; rr += rred[w]; }
        g_Spart[blockIdx.x]  = ss;    // plain stores, no init needed
        g_R2part[blockIdx.x] = rr;
    }

    // Block exclusively owns slice (sub, t): plain vector stores.
    float4* __restrict__ qp = (float4*)g_Qpart[sub][t];
    const float4* __restrict__ qsv = (const float4*)qs;
    for (int j = tid; j < C1V / 4; j += THREADS) qp[j] = qsv[j];
}

// ---------------------------------------------------------------------------
// Pass 2 + finalize (fused via last-block ticket).
// grid = 128 blocks, one per t: combine the 8 Q slices -> Q2[t], Sbar[t].
// Last block to finish reduces all partials in double and writes the loss.
// ---------------------------------------------------------------------------
__global__ __launch_bounds__(256) void lcl_pass2(float* __restrict__ out) {
    __shared__ float  redA[256];
    __shared__ float  redB[256];
    __shared__ double dred[4][32];
    __shared__ bool   amLast;

    const int t = blockIdx.x, tid = threadIdx.x;
    const int warp = tid >> 5, lane = tid & 31;

    float sq2 = 0.f, sb = 0.f;
    for (int j = tid; j < C1V; j += 256) {
        float v = 0.f;
#pragma unroll
        for (int s = 0; s < BLOCKS_PER_T; s++) v += g_Qpart[s][t][j];
        sq2 += v * v;
        sb  += v;
    }
    redA[tid] = sq2; redB[tid] = sb;
    __syncthreads();
    for (int s = 128; s > 0; s >>= 1) {
        if (tid < s) { redA[tid] += redA[tid + s]; redB[tid] += redB[tid + s]; }
        __syncthreads();
    }
    if (tid == 0) {
        g_Q2part[t] = redA[0];
        g_SBpart[t] = redB[0];
        __threadfence();
        int prev = atomicAdd(&g_ticket, 1);
        amLast = (prev == TV - 1);
    }
    __syncthreads();
    if (!amLast) return;
    __threadfence();   // acquire: see all blocks' partial stores

    // ---- final reduction, double precision ----
    double dS = 0.0, dR2 = 0.0, dQ2 = 0.0, dSB2 = 0.0;
    for (int b = tid; b < GRID1; b += 256) {
        dS  += (double)g_Spart[b];
        dR2 += (double)g_R2part[b];
    }
    for (int j = tid; j < TV; j += 256) {
        dQ2 += (double)g_Q2part[j];
        double sbv = (double)g_SBpart[j];
        dSB2 += sbv * sbv;
    }
#pragma unroll
    for (int o = 16; o > 0; o >>= 1) {
        dS   += __shfl_xor_sync(0xffffffffu, dS,  o);
        dR2  += __shfl_xor_sync(0xffffffffu, dR2, o);
        dQ2  += __shfl_xor_sync(0xffffffffu, dQ2, o);
        dSB2 += __shfl_xor_sync(0xffffffffu, dSB2, o);
    }
    if (lane == 0) {
        dred[0][warp] = dS;  dred[1][warp] = dR2;
        dred[2][warp] = dQ2; dred[3][warp] = dSB2;
    }
    __syncthreads();
    if (tid == 0) {
        double S = 0, R2 = 0, Q2 = 0, SB2 = 0;
#pragma unroll
        for (int w = 0; w < 8; w++) {
            S += dred[0][w]; R2 += dred[1][w]; Q2 += dred[2][w]; SB2 += dred[3][w];
        }
        const double c0 = (double)C0V, c1 = (double)C1V;
        const double intra  = S - R2 / c1;
        const double inter  = R2 / c1 - SB2 / (c0 * c1);
        const double dintra = S - Q2 / c0;
        const double dinter = Q2 / c0 - SB2 / (c0 * c1);
        out[0] = (float)(0.5 * (intra / inter + dintra / dinter) / (c0 * c1));
        g_ticket = 0;        // reset for the next graph replay (deterministic)
    }
}

extern "C" void kernel_launch(void* const* d_in, const int* in_sizes, int n_in,
                              void* d_out, int out_size) {
    const float* in = (const float*)d_in[0];
    float* out = (float*)d_out;
    (void)in_sizes; (void)n_in; (void)out_size;

    lcl_pass1<<<GRID1, THREADS>>>(in);
    lcl_pass2<<<TV, 256>>>(out);
}